// round 1
// baseline (speedup 1.0000x reference)
#include <cuda_runtime.h>

#define N_TOOLS 50
#define DIM 512
#define N_TOKENS 8192
#define PARAM_DIM 256

// Expert grouping scratch (device globals: no allocations allowed)
__device__ int g_count[N_TOOLS];
__device__ int g_tokens[N_TOOLS * N_TOKENS];

__global__ void zero_counts_kernel() {
    if (threadIdx.x < N_TOOLS) g_count[threadIdx.x] = 0;
}

// ---------------------------------------------------------------------------
// Router: logits = x @ rw^T + rb ; softmax ; argmax ; group tokens by expert
// One block = 128 tokens, 256 threads. Thread pair covers one token row,
// each thread 25 of the 50 tools.
// ---------------------------------------------------------------------------
__global__ void router_kernel(const float* __restrict__ x,
                              const float* __restrict__ rw,
                              const float* __restrict__ rb,
                              float* __restrict__ out_idx,
                              float* __restrict__ out_probs) {
    __shared__ float Xs[32][128];     // [k][m]
    __shared__ float Ws[N_TOOLS][32]; // [n][k]
    __shared__ float Ls[128][N_TOOLS];
    __shared__ float Bs[N_TOOLS];

    const int tid = threadIdx.x;
    const int row0 = blockIdx.x * 128;
    if (tid < N_TOOLS) Bs[tid] = rb[tid];

    const int rm = tid >> 1;
    const int half = (tid & 1) * 25;
    float acc[25];
#pragma unroll
    for (int j = 0; j < 25; j++) acc[j] = 0.f;

    for (int k0 = 0; k0 < DIM; k0 += 32) {
        __syncthreads();
        // X tile: 128 rows x 32 k = 1024 float4
#pragma unroll
        for (int t = 0; t < 4; t++) {
            int j = tid + t * 256;
            int m = j >> 3;
            int kq = (j & 7) * 4;
            float4 v = *(const float4*)&x[(size_t)(row0 + m) * DIM + k0 + kq];
            Xs[kq + 0][m] = v.x; Xs[kq + 1][m] = v.y;
            Xs[kq + 2][m] = v.z; Xs[kq + 3][m] = v.w;
        }
        // W tile: 50 x 32 = 400 float4
        for (int j = tid; j < 400; j += 256) {
            int n = j >> 3;
            int kq = (j & 7) * 4;
            float4 v = *(const float4*)&rw[(size_t)n * DIM + k0 + kq];
            Ws[n][kq + 0] = v.x; Ws[n][kq + 1] = v.y;
            Ws[n][kq + 2] = v.z; Ws[n][kq + 3] = v.w;
        }
        __syncthreads();
#pragma unroll
        for (int k = 0; k < 32; k++) {
            float xv = Xs[k][rm];
#pragma unroll
            for (int j = 0; j < 25; j++) acc[j] += xv * Ws[half + j][k];
        }
    }
#pragma unroll
    for (int j = 0; j < 25; j++) Ls[rm][half + j] = acc[j];
    __syncthreads();

    if (tid < 128) {
        const int row = row0 + tid;
        float lg[N_TOOLS];
        float best = -1e30f;
        int bi = 0;
#pragma unroll
        for (int j = 0; j < N_TOOLS; j++) {
            float v = Ls[tid][j] + Bs[j];
            lg[j] = v;
            if (v > best) { best = v; bi = j; }  // first-occurrence argmax
        }
        float s = 0.f;
#pragma unroll
        for (int j = 0; j < N_TOOLS; j++) { lg[j] = expf(lg[j] - best); s += lg[j]; }
        float inv = 1.f / s;
#pragma unroll
        for (int j = 0; j < N_TOOLS; j++) out_probs[(size_t)row * N_TOOLS + j] = lg[j] * inv;
        out_idx[row] = (float)bi;
        int pos = atomicAdd(&g_count[bi], 1);
        g_tokens[bi * N_TOKENS + pos] = row;
    }
}

// ---------------------------------------------------------------------------
// Params head: C[8192,256] = X[8192,512] @ Pw[256,512]^T + pb
// BM=64, BN=64, BK=32, 256 threads, 4x4 micro-tile per thread.
// ---------------------------------------------------------------------------
__global__ void params_kernel(const float* __restrict__ x,
                              const float* __restrict__ pw,
                              const float* __restrict__ pb,
                              float* __restrict__ out) {
    __shared__ float Xs[32][64];  // [k][m]
    __shared__ float Ws[32][64];  // [k][n]

    const int tid = threadIdx.x;
    const int ntile = blockIdx.x;   // 0..3
    const int mtile = blockIdx.y;   // 0..127
    const int tx = tid & 15, ty = tid >> 4;
    const float* W = pw + (size_t)(ntile * 64) * DIM;
    const int row0 = mtile * 64;

    float acc[4][4];
#pragma unroll
    for (int i = 0; i < 4; i++)
#pragma unroll
        for (int j = 0; j < 4; j++) acc[i][j] = 0.f;

    for (int k0 = 0; k0 < DIM; k0 += 32) {
        __syncthreads();
#pragma unroll
        for (int t = 0; t < 2; t++) {
            int j = tid + t * 256;
            int m = j >> 3, kq = (j & 7) * 4;
            float4 v = *(const float4*)&x[(size_t)(row0 + m) * DIM + k0 + kq];
            Xs[kq + 0][m] = v.x; Xs[kq + 1][m] = v.y;
            Xs[kq + 2][m] = v.z; Xs[kq + 3][m] = v.w;
        }
#pragma unroll
        for (int t = 0; t < 2; t++) {
            int j = tid + t * 256;
            int n = j >> 3, kq = (j & 7) * 4;
            float4 v = *(const float4*)&W[(size_t)n * DIM + k0 + kq];
            Ws[kq + 0][n] = v.x; Ws[kq + 1][n] = v.y;
            Ws[kq + 2][n] = v.z; Ws[kq + 3][n] = v.w;
        }
        __syncthreads();
#pragma unroll
        for (int k = 0; k < 32; k++) {
            float4 a = *(const float4*)&Xs[k][ty * 4];
            float4 b = *(const float4*)&Ws[k][tx * 4];
            float av[4] = {a.x, a.y, a.z, a.w};
            float bv[4] = {b.x, b.y, b.z, b.w};
#pragma unroll
            for (int i = 0; i < 4; i++)
#pragma unroll
                for (int j = 0; j < 4; j++) acc[i][j] += av[i] * bv[j];
        }
    }

    const int nbase = ntile * 64 + tx * 4;
    float4 bb = *(const float4*)&pb[nbase];
    float bv[4] = {bb.x, bb.y, bb.z, bb.w};
#pragma unroll
    for (int i = 0; i < 4; i++) {
        int r = row0 + ty * 4 + i;
        float4 o;
        o.x = acc[i][0] + bv[0];
        o.y = acc[i][1] + bv[1];
        o.z = acc[i][2] + bv[2];
        o.w = acc[i][3] + bv[3];
        *(float4*)&out[(size_t)r * PARAM_DIM + nbase] = o;
    }
}

// ---------------------------------------------------------------------------
// Adapted: per (expert, m-tile, n-tile): Y = gather(X) @ We^T + be, scattered
// back to token rows. Same GEMM shape as params_kernel + gather/scatter.
// ---------------------------------------------------------------------------
__global__ void adapted_kernel(const float* __restrict__ x,
                               const float* __restrict__ ew,
                               const float* __restrict__ eb,
                               float* __restrict__ out) {
    const int e = blockIdx.z;
    const int ntile = blockIdx.x;   // 0..7
    const int mtile = blockIdx.y;   // 0..127
    const int cnt = g_count[e];
    if (mtile * 64 >= cnt) return;

    __shared__ float Xs[32][64];
    __shared__ float Ws[32][64];
    __shared__ int ridx[64];

    const int tid = threadIdx.x;
    if (tid < 64) {
        int p = mtile * 64 + tid;
        ridx[tid] = (p < cnt) ? g_tokens[e * N_TOKENS + p] : -1;
    }

    const float* W = ew + (size_t)e * DIM * DIM + (size_t)(ntile * 64) * DIM;
    const int tx = tid & 15, ty = tid >> 4;

    float acc[4][4];
#pragma unroll
    for (int i = 0; i < 4; i++)
#pragma unroll
        for (int j = 0; j < 4; j++) acc[i][j] = 0.f;

    for (int k0 = 0; k0 < DIM; k0 += 32) {
        __syncthreads();
#pragma unroll
        for (int t = 0; t < 2; t++) {
            int j = tid + t * 256;
            int m = j >> 3, kq = (j & 7) * 4;
            int r = ridx[m];
            float4 v = (r >= 0) ? *(const float4*)&x[(size_t)r * DIM + k0 + kq]
                                : make_float4(0.f, 0.f, 0.f, 0.f);
            Xs[kq + 0][m] = v.x; Xs[kq + 1][m] = v.y;
            Xs[kq + 2][m] = v.z; Xs[kq + 3][m] = v.w;
        }
#pragma unroll
        for (int t = 0; t < 2; t++) {
            int j = tid + t * 256;
            int n = j >> 3, kq = (j & 7) * 4;
            float4 v = *(const float4*)&W[(size_t)n * DIM + k0 + kq];
            Ws[kq + 0][n] = v.x; Ws[kq + 1][n] = v.y;
            Ws[kq + 2][n] = v.z; Ws[kq + 3][n] = v.w;
        }
        __syncthreads();
#pragma unroll
        for (int k = 0; k < 32; k++) {
            float4 a = *(const float4*)&Xs[k][ty * 4];
            float4 b = *(const float4*)&Ws[k][tx * 4];
            float av[4] = {a.x, a.y, a.z, a.w};
            float bv[4] = {b.x, b.y, b.z, b.w};
#pragma unroll
            for (int i = 0; i < 4; i++)
#pragma unroll
                for (int j = 0; j < 4; j++) acc[i][j] += av[i] * bv[j];
        }
    }

    const int nbase = ntile * 64 + tx * 4;
    float4 bb = *(const float4*)&eb[(size_t)e * DIM + nbase];
    float bv[4] = {bb.x, bb.y, bb.z, bb.w};
#pragma unroll
    for (int i = 0; i < 4; i++) {
        int r = ridx[ty * 4 + i];
        if (r >= 0) {
            float4 o;
            o.x = acc[i][0] + bv[0];
            o.y = acc[i][1] + bv[1];
            o.z = acc[i][2] + bv[2];
            o.w = acc[i][3] + bv[3];
            *(float4*)&out[(size_t)r * DIM + nbase] = o;
        }
    }
}

// ---------------------------------------------------------------------------
extern "C" void kernel_launch(void* const* d_in, const int* in_sizes, int n_in,
                              void* d_out, int out_size) {
    const float* x  = (const float*)d_in[0];
    const float* rw = (const float*)d_in[1];
    const float* rb = (const float*)d_in[2];
    const float* ew = (const float*)d_in[3];
    const float* eb = (const float*)d_in[4];
    const float* pw = (const float*)d_in[5];
    const float* pb = (const float*)d_in[6];

    float* out      = (float*)d_out;
    float* o_idx    = out;                                     // 8192
    float* o_probs  = out + N_TOKENS;                          // 8192*50
    float* o_adapt  = o_probs + (size_t)N_TOKENS * N_TOOLS;    // 8192*512
    float* o_params = o_adapt + (size_t)N_TOKENS * DIM;        // 8192*256

    zero_counts_kernel<<<1, 64>>>();
    router_kernel<<<N_TOKENS / 128, 256>>>(x, rw, rb, o_idx, o_probs);
    params_kernel<<<dim3(PARAM_DIM / 64, N_TOKENS / 64), 256>>>(x, pw, pb, o_params);
    adapted_kernel<<<dim3(DIM / 64, N_TOKENS / 64, N_TOOLS), 256>>>(x, ew, eb, o_adapt);
}

// round 3
// speedup vs baseline: 2.2427x; 2.2427x over previous
#include <cuda_runtime.h>
#include <cstdint>

#define N_TOOLS 50
#define DIM 512
#define N_TOKENS 8192
#define PARAM_DIM 256

// GEMM tiling
#define BM 64
#define BN 128
#define BK 16
#define KSTAGES (DIM / BK)   // 32

// Expert grouping scratch (no allocations allowed -> device globals)
__device__ int g_count[N_TOOLS];
__device__ int g_tokens[N_TOOLS * N_TOKENS];

__global__ void zero_counts_kernel() {
    if (threadIdx.x < N_TOOLS) g_count[threadIdx.x] = 0;
}

// ======================= helpers =========================================
__device__ __forceinline__ uint32_t f2tf32(float x) {
    uint32_t r;
    asm("cvt.rna.tf32.f32 %0, %1;" : "=r"(r) : "f"(x));
    return r;
}
__device__ __forceinline__ uint4 cvt4(float4 v) {
    uint4 o;
    o.x = f2tf32(v.x); o.y = f2tf32(v.y);
    o.z = f2tf32(v.z); o.w = f2tf32(v.w);
    return o;
}
__device__ __forceinline__ void mma_tf32(float* c, const uint32_t* a,
                                         const uint32_t* b) {
    asm volatile(
        "mma.sync.aligned.m16n8k8.row.col.f32.tf32.tf32.f32 "
        "{%0,%1,%2,%3}, {%4,%5,%6,%7}, {%8,%9}, {%0,%1,%2,%3};"
        : "+f"(c[0]), "+f"(c[1]), "+f"(c[2]), "+f"(c[3])
        : "r"(a[0]), "r"(a[1]), "r"(a[2]), "r"(a[3]), "r"(b[0]), "r"(b[1]));
}

// SMEM swizzle: 16 words/row; quad q of row r lives at quad (q + r + (r>>2)) & 3.
// Conflict-free for both STS.128 fills and the mma fragment scalar loads.
__device__ __forceinline__ int st_off(int row, int q4) {
    return row * 16 + (((q4 + row + (row >> 2)) & 3) << 2);
}
__device__ __forceinline__ int ld_off(int row, int colq, int tg) {
    return row * 16 + (((colq + row + (row >> 2)) & 3) << 2) + tg;
}

// ======================= router (exact fp32) ==============================
__global__ void router_kernel(const float* __restrict__ x,
                              const float* __restrict__ rw,
                              const float* __restrict__ rb,
                              float* __restrict__ out_idx,
                              float* __restrict__ out_probs) {
    __shared__ float Xs[32][64];
    __shared__ float Ws[N_TOOLS][32];
    __shared__ float Ls[64][52];
    __shared__ float Bs[N_TOOLS];

    const int tid = threadIdx.x;
    const int row0 = blockIdx.x * 64;
    if (tid < N_TOOLS) Bs[tid] = rb[tid];

    const int rm = tid >> 1;
    const int half = (tid & 1) * 25;
    float acc[25];
#pragma unroll
    for (int j = 0; j < 25; j++) acc[j] = 0.f;

    for (int k0 = 0; k0 < DIM; k0 += 32) {
        __syncthreads();
#pragma unroll
        for (int t = 0; t < 4; t++) {
            int j = tid + t * 128;
            int m = j >> 3, kq = (j & 7) * 4;
            float4 v = *(const float4*)&x[(size_t)(row0 + m) * DIM + k0 + kq];
            Xs[kq + 0][m] = v.x; Xs[kq + 1][m] = v.y;
            Xs[kq + 2][m] = v.z; Xs[kq + 3][m] = v.w;
        }
        for (int j = tid; j < 400; j += 128) {
            int n = j >> 3, kq = (j & 7) * 4;
            float4 v = *(const float4*)&rw[(size_t)n * DIM + k0 + kq];
            Ws[n][kq + 0] = v.x; Ws[n][kq + 1] = v.y;
            Ws[n][kq + 2] = v.z; Ws[n][kq + 3] = v.w;
        }
        __syncthreads();
#pragma unroll
        for (int k = 0; k < 32; k++) {
            float xv = Xs[k][rm];
#pragma unroll
            for (int j = 0; j < 25; j++) acc[j] += xv * Ws[half + j][k];
        }
    }
#pragma unroll
    for (int j = 0; j < 25; j++) Ls[rm][half + j] = acc[j];
    __syncthreads();

    if (tid < 64) {
        const int row = row0 + tid;
        float lg[N_TOOLS];
        float best = -1e30f;
        int bi = 0;
#pragma unroll
        for (int j = 0; j < N_TOOLS; j++) {
            float v = Ls[tid][j] + Bs[j];
            lg[j] = v;
            if (v > best) { best = v; bi = j; }
        }
        float s = 0.f;
#pragma unroll
        for (int j = 0; j < N_TOOLS; j++) { lg[j] = expf(lg[j] - best); s += lg[j]; }
        float inv = 1.f / s;
#pragma unroll
        for (int j = 0; j < N_TOOLS; j++)
            out_probs[(size_t)row * N_TOOLS + j] = lg[j] * inv;
        out_idx[row] = (float)bi;
        int pos = atomicAdd(&g_count[bi], 1);
        g_tokens[bi * N_TOKENS + pos] = row;
    }
}

// ======================= tf32 tensor-core GEMM ============================
// C[BM=64, BN=128] tile of  Y = X @ W^T + b.  128 threads = 4 warps,
// warp tile 32x64 (2 m-frags x 8 n-frags of m16n8k8).
// GATHER: rows come from g_tokens[expert]; result scattered back.
template <bool GATHER>
__global__ void __launch_bounds__(128, 2)
tc_gemm_kernel(const float* __restrict__ X, const float* __restrict__ Wg,
               const float* __restrict__ Bg, float* __restrict__ out,
               int out_ld) {
    __shared__ uint32_t As[2][BM * 16];
    __shared__ uint32_t Bs[2][BN * 16];
    __shared__ float bsh[BN];
    __shared__ int ridx[BM];

    const int tid = threadIdx.x;
    const int lane = tid & 31;
    const int warp = tid >> 5;
    const int g = lane >> 2, tg = lane & 3;
    const int wm = (warp >> 1) * 32;       // 0 or 32
    const int wn = (warp & 1) * 64;        // 0 or 64
    const int n0 = blockIdx.x * BN;

    const float* W;
    const float* bias;
    int row0 = 0;

    if (GATHER) {
        const int e = blockIdx.z;
        const int cnt = g_count[e];
        if ((int)blockIdx.y * BM >= cnt) return;
        W = Wg + (size_t)e * DIM * DIM + (size_t)n0 * DIM;
        bias = Bg + (size_t)e * DIM;
        if (tid < BM) {
            int p = blockIdx.y * BM + tid;
            ridx[tid] = g_tokens[e * N_TOKENS + (p < cnt ? p : cnt - 1)];
        }
    } else {
        W = Wg + (size_t)n0 * DIM;
        bias = Bg;
        row0 = blockIdx.y * BM;
    }
    bsh[tid] = bias[n0 + tid];   // BN == blockDim.x == 128
    __syncthreads();

    // ---- per-thread gmem load setup ----
    const int qk = (tid & 3) * 4;          // k offset of this thread's float4
    const int ar0 = tid >> 2;              // A rows 0..31 (+32 on 2nd)
    int gr_a0, gr_a1;
    if (GATHER) { gr_a0 = ridx[ar0]; gr_a1 = ridx[ar0 + 32]; }
    else        { gr_a0 = row0 + ar0; gr_a1 = row0 + ar0 + 32; }
    const float* aP0 = X + (size_t)gr_a0 * DIM + qk;
    const float* aP1 = X + (size_t)gr_a1 * DIM + qk;
    const float* bP0 = W + (size_t)(ar0 +  0) * DIM + qk;
    const float* bP1 = W + (size_t)(ar0 + 32) * DIM + qk;
    const float* bP2 = W + (size_t)(ar0 + 64) * DIM + qk;
    const float* bP3 = W + (size_t)(ar0 + 96) * DIM + qk;

    const int sa0 = st_off(ar0,      tid & 3);
    const int sa1 = st_off(ar0 + 32, tid & 3);
    const int sb0 = st_off(ar0,      tid & 3);
    const int sb1 = st_off(ar0 + 32, tid & 3);
    const int sb2 = st_off(ar0 + 64, tid & 3);
    const int sb3 = st_off(ar0 + 96, tid & 3);

    float acc[2][8][4];
#pragma unroll
    for (int mt = 0; mt < 2; mt++)
#pragma unroll
        for (int nt = 0; nt < 8; nt++)
#pragma unroll
            for (int i = 0; i < 4; i++) acc[mt][nt][i] = 0.f;

    // ---- stage 0 fill ----
    {
        float4 va0 = *(const float4*)(aP0);
        float4 va1 = *(const float4*)(aP1);
        float4 vb0 = *(const float4*)(bP0);
        float4 vb1 = *(const float4*)(bP1);
        float4 vb2 = *(const float4*)(bP2);
        float4 vb3 = *(const float4*)(bP3);
        *(uint4*)&As[0][sa0] = cvt4(va0);
        *(uint4*)&As[0][sa1] = cvt4(va1);
        *(uint4*)&Bs[0][sb0] = cvt4(vb0);
        *(uint4*)&Bs[0][sb1] = cvt4(vb1);
        *(uint4*)&Bs[0][sb2] = cvt4(vb2);
        *(uint4*)&Bs[0][sb3] = cvt4(vb3);
    }
    __syncthreads();

    for (int kt = 0; kt < KSTAGES; kt++) {
        const int buf = kt & 1;
        float4 va0, va1, vb0, vb1, vb2, vb3;
        if (kt + 1 < KSTAGES) {
            const int ko = (kt + 1) * BK;
            va0 = *(const float4*)(aP0 + ko);
            va1 = *(const float4*)(aP1 + ko);
            vb0 = *(const float4*)(bP0 + ko);
            vb1 = *(const float4*)(bP1 + ko);
            vb2 = *(const float4*)(bP2 + ko);
            vb3 = *(const float4*)(bP3 + ko);
        }
        // compute on buf
#pragma unroll
        for (int ks = 0; ks < 2; ks++) {
            uint32_t af[2][4];
#pragma unroll
            for (int mt = 0; mt < 2; mt++) {
                const int rA = wm + mt * 16 + g;
                af[mt][0] = As[buf][ld_off(rA,     2 * ks,     tg)];
                af[mt][1] = As[buf][ld_off(rA + 8, 2 * ks,     tg)];
                af[mt][2] = As[buf][ld_off(rA,     2 * ks + 1, tg)];
                af[mt][3] = As[buf][ld_off(rA + 8, 2 * ks + 1, tg)];
            }
#pragma unroll
            for (int nt = 0; nt < 8; nt++) {
                const int rB = wn + nt * 8 + g;
                uint32_t bf[2];
                bf[0] = Bs[buf][ld_off(rB, 2 * ks,     tg)];
                bf[1] = Bs[buf][ld_off(rB, 2 * ks + 1, tg)];
                mma_tf32(acc[0][nt], af[0], bf);
                mma_tf32(acc[1][nt], af[1], bf);
            }
        }
        if (kt + 1 < KSTAGES) {
            const int nb = buf ^ 1;
            *(uint4*)&As[nb][sa0] = cvt4(va0);
            *(uint4*)&As[nb][sa1] = cvt4(va1);
            *(uint4*)&Bs[nb][sb0] = cvt4(vb0);
            *(uint4*)&Bs[nb][sb1] = cvt4(vb1);
            *(uint4*)&Bs[nb][sb2] = cvt4(vb2);
            *(uint4*)&Bs[nb][sb3] = cvt4(vb3);
        }
        __syncthreads();
    }

    // ---- epilogue: bias + scatter/store (duplicate padded rows write
    //      identical values -> deterministic) ----
#pragma unroll
    for (int mt = 0; mt < 2; mt++) {
        const int lr0 = wm + mt * 16 + g;
        const int lr1 = lr0 + 8;
        int gr0, gr1;
        if (GATHER) { gr0 = ridx[lr0]; gr1 = ridx[lr1]; }
        else        { gr0 = row0 + lr0; gr1 = row0 + lr1; }
        float* o0 = out + (size_t)gr0 * out_ld + n0;
        float* o1 = out + (size_t)gr1 * out_ld + n0;
#pragma unroll
        for (int nt = 0; nt < 8; nt++) {
            const int c = wn + nt * 8 + 2 * tg;
            float2 s0, s1;
            s0.x = acc[mt][nt][0] + bsh[c];
            s0.y = acc[mt][nt][1] + bsh[c + 1];
            s1.x = acc[mt][nt][2] + bsh[c];
            s1.y = acc[mt][nt][3] + bsh[c + 1];
            *(float2*)(o0 + c) = s0;
            *(float2*)(o1 + c) = s1;
        }
    }
}

// ===========================================================================
extern "C" void kernel_launch(void* const* d_in, const int* in_sizes, int n_in,
                              void* d_out, int out_size) {
    const float* x  = (const float*)d_in[0];
    const float* rw = (const float*)d_in[1];
    const float* rb = (const float*)d_in[2];
    const float* ew = (const float*)d_in[3];
    const float* eb = (const float*)d_in[4];
    const float* pw = (const float*)d_in[5];
    const float* pb = (const float*)d_in[6];

    float* out      = (float*)d_out;
    float* o_idx    = out;
    float* o_probs  = out + N_TOKENS;
    float* o_adapt  = o_probs + (size_t)N_TOKENS * N_TOOLS;
    float* o_params = o_adapt + (size_t)N_TOKENS * DIM;

    zero_counts_kernel<<<1, 64>>>();
    router_kernel<<<N_TOKENS / 64, 128>>>(x, rw, rb, o_idx, o_probs);
    tc_gemm_kernel<true><<<dim3(DIM / BN, N_TOKENS / BM, N_TOOLS), 128>>>(
        x, ew, eb, o_adapt, DIM);
    tc_gemm_kernel<false><<<dim3(PARAM_DIM / BN, N_TOKENS / BM, 1), 128>>>(
        x, pw, pb, o_params, PARAM_DIM);
}

// round 4
// speedup vs baseline: 2.3349x; 1.0411x over previous
#include <cuda_runtime.h>
#include <cstdint>

#define N_TOOLS 50
#define DIM 512
#define N_TOKENS 8192
#define PARAM_DIM 256

// --------------------- device scratch (no allocs allowed) ------------------
__device__ int g_count[N_TOOLS];
__device__ int g_tokens[N_TOOLS * N_TOKENS];
__device__ int g_ntiles;
__device__ int g_tile_e[256];
__device__ int g_tile_m[256];

__global__ void zero_counts_kernel() {
    if (threadIdx.x < N_TOOLS) g_count[threadIdx.x] = 0;
}

// Build compact (expert, mtile) work list for the adapted GEMM (BM=64).
__global__ void build_tiles_kernel() {
    if (threadIdx.x == 0) {
        int t = 0;
        for (int e = 0; e < N_TOOLS; e++) {
            int tiles = (g_count[e] + 63) >> 6;
            for (int m = 0; m < tiles; m++) {
                g_tile_e[t] = e;
                g_tile_m[t] = m;
                t++;
            }
        }
        g_ntiles = t;
    }
}

// ----------------------------- helpers ------------------------------------
__device__ __forceinline__ uint32_t f2tf32(float x) {
    uint32_t r;
    asm("cvt.rna.tf32.f32 %0, %1;" : "=r"(r) : "f"(x));
    return r;
}
__device__ __forceinline__ void mma_tf32(float* c, const uint32_t* a,
                                         const uint32_t* b) {
    asm volatile(
        "mma.sync.aligned.m16n8k8.row.col.f32.tf32.tf32.f32 "
        "{%0,%1,%2,%3}, {%4,%5,%6,%7}, {%8,%9}, {%0,%1,%2,%3};"
        : "+f"(c[0]), "+f"(c[1]), "+f"(c[2]), "+f"(c[3])
        : "r"(a[0]), "r"(a[1]), "r"(a[2]), "r"(a[3]), "r"(b[0]), "r"(b[1]));
}

// ======================= router (exact fp32) ==============================
__global__ void router_kernel(const float* __restrict__ x,
                              const float* __restrict__ rw,
                              const float* __restrict__ rb,
                              float* __restrict__ out_idx,
                              float* __restrict__ out_probs) {
    __shared__ float Xs[32][64];
    __shared__ float Ws[N_TOOLS][32];
    __shared__ float Ls[64][52];
    __shared__ float Bs[N_TOOLS];

    const int tid = threadIdx.x;
    const int row0 = blockIdx.x * 64;
    if (tid < N_TOOLS) Bs[tid] = rb[tid];

    const int rm = tid >> 1;
    const int half = (tid & 1) * 25;
    float acc[25];
#pragma unroll
    for (int j = 0; j < 25; j++) acc[j] = 0.f;

    for (int k0 = 0; k0 < DIM; k0 += 32) {
        __syncthreads();
#pragma unroll
        for (int t = 0; t < 4; t++) {
            int j = tid + t * 128;
            int m = j >> 3, kq = (j & 7) * 4;
            float4 v = *(const float4*)&x[(size_t)(row0 + m) * DIM + k0 + kq];
            Xs[kq + 0][m] = v.x; Xs[kq + 1][m] = v.y;
            Xs[kq + 2][m] = v.z; Xs[kq + 3][m] = v.w;
        }
        for (int j = tid; j < 400; j += 128) {
            int n = j >> 3, kq = (j & 7) * 4;
            float4 v = *(const float4*)&rw[(size_t)n * DIM + k0 + kq];
            Ws[n][kq + 0] = v.x; Ws[n][kq + 1] = v.y;
            Ws[n][kq + 2] = v.z; Ws[n][kq + 3] = v.w;
        }
        __syncthreads();
#pragma unroll
        for (int k = 0; k < 32; k++) {
            float xv = Xs[k][rm];
#pragma unroll
            for (int j = 0; j < 25; j++) acc[j] += xv * Ws[half + j][k];
        }
    }
#pragma unroll
    for (int j = 0; j < 25; j++) Ls[rm][half + j] = acc[j];
    __syncthreads();

    if (tid < 64) {
        const int row = row0 + tid;
        float lg[N_TOOLS];
        float best = -1e30f;
        int bi = 0;
#pragma unroll
        for (int j = 0; j < N_TOOLS; j++) {
            float v = Ls[tid][j] + Bs[j];
            lg[j] = v;
            if (v > best) { best = v; bi = j; }
        }
        float s = 0.f;
#pragma unroll
        for (int j = 0; j < N_TOOLS; j++) { lg[j] = expf(lg[j] - best); s += lg[j]; }
        float inv = 1.f / s;
#pragma unroll
        for (int j = 0; j < N_TOOLS; j++)
            out_probs[(size_t)row * N_TOOLS + j] = lg[j] * inv;
        out_idx[row] = (float)bi;
        int pos = atomicAdd(&g_count[bi], 1);
        g_tokens[bi * N_TOKENS + pos] = row;
    }
}

// ======================= tf32 tensor-core GEMM ============================
// Y[BM, BN] tile of X @ W^T + b.  256 threads = 8 warps (BM/32 x BN/32 grid
// of 32x32 warp tiles).  BK=32, double-buffered smem.
// SMEM layout per tile row r (32 k-words): word = r*36 + ((c&3)^(r&3))*8 + (c>>2)
//   -> fragment loads are conflict-free LDS.128 covering a full k16.
template <int BM, int BN, bool GATHER>
__global__ void __launch_bounds__(256, 2)
tc_gemm(const float* __restrict__ X, const float* __restrict__ Wg,
        const float* __restrict__ Bg, float* __restrict__ out, int out_ld) {
    constexpr int STAGE = (BM + BN) * 36;   // words per stage
    constexpr int NA = BM / 32;             // float4 loads per thread (A)
    constexpr int NB = BN / 32;             // float4 loads per thread (B)
    constexpr int MW = BM / 32;             // warp grid m-dim

    extern __shared__ uint32_t sm[];
    float* bias = (float*)(sm + 2 * STAGE);
    int* ridx = (int*)(sm + 2 * STAGE + BN);

    const int tid = threadIdx.x;
    const int lane = tid & 31, warp = tid >> 5;
    const int g = lane >> 2, tg = lane & 3;
    const int wm = (warp % MW) * 32;
    const int wn = (warp / MW) * 32;
    const int n0 = blockIdx.x * BN;

    const float* W;
    const float* bsrc;
    int row0 = 0;

    if (GATHER) {
        const int ty = blockIdx.y;
        if (ty >= g_ntiles) return;
        const int e = g_tile_e[ty];
        const int mtile = g_tile_m[ty];
        const int cnt = g_count[e];
        W = Wg + (size_t)e * DIM * DIM + (size_t)n0 * DIM;
        bsrc = Bg + (size_t)e * DIM;
        if (tid < BM) {
            int p = mtile * BM + tid;
            ridx[tid] = g_tokens[e * N_TOKENS + (p < cnt ? p : cnt - 1)];
        }
    } else {
        W = Wg + (size_t)n0 * DIM;
        bsrc = Bg;
        row0 = blockIdx.y * BM;
    }
    if (tid < BN) bias[tid] = bsrc[n0 + tid];
    __syncthreads();

    // ---- loader setup: thread i covers (row = f>>3, quad q = f&7) ----
    int aoff[NA], asts[NA], ax3[NA];
    int boff[NB], bsts[NB], bx3[NB];
#pragma unroll
    for (int i = 0; i < NA; i++) {
        int f = tid + i * 256;
        int r = f >> 3, q = f & 7;
        int gr = GATHER ? ridx[r] : row0 + r;
        aoff[i] = gr * DIM + q * 4;
        asts[i] = r * 36 + q;
        ax3[i] = r & 3;
    }
#pragma unroll
    for (int i = 0; i < NB; i++) {
        int f = tid + i * 256;
        int r = f >> 3, q = f & 7;
        boff[i] = r * DIM + q * 4;
        bsts[i] = r * 36 + q;
        bx3[i] = r & 3;
    }

    float4 pa[NA], pb[NB];
#pragma unroll
    for (int i = 0; i < NA; i++) pa[i] = *(const float4*)(X + aoff[i]);
#pragma unroll
    for (int i = 0; i < NB; i++) pb[i] = *(const float4*)(W + boff[i]);

    // store stage 0
    {
        uint32_t* Sa = sm;
        uint32_t* Sb = sm + BM * 36;
#pragma unroll
        for (int i = 0; i < NA; i++) {
            Sa[asts[i] + ((0 ^ ax3[i]) << 3)] = f2tf32(pa[i].x);
            Sa[asts[i] + ((1 ^ ax3[i]) << 3)] = f2tf32(pa[i].y);
            Sa[asts[i] + ((2 ^ ax3[i]) << 3)] = f2tf32(pa[i].z);
            Sa[asts[i] + ((3 ^ ax3[i]) << 3)] = f2tf32(pa[i].w);
        }
#pragma unroll
        for (int i = 0; i < NB; i++) {
            Sb[bsts[i] + ((0 ^ bx3[i]) << 3)] = f2tf32(pb[i].x);
            Sb[bsts[i] + ((1 ^ bx3[i]) << 3)] = f2tf32(pb[i].y);
            Sb[bsts[i] + ((2 ^ bx3[i]) << 3)] = f2tf32(pb[i].z);
            Sb[bsts[i] + ((3 ^ bx3[i]) << 3)] = f2tf32(pb[i].w);
        }
    }
    __syncthreads();

    float acc[2][4][4];
#pragma unroll
    for (int mt = 0; mt < 2; mt++)
#pragma unroll
        for (int nt = 0; nt < 4; nt++)
#pragma unroll
            for (int i = 0; i < 4; i++) acc[mt][nt][i] = 0.f;

    const int slot8 = (tg ^ (g & 3)) << 3;   // r&3 == g&3 for all frag rows

    for (int kt = 0; kt < 16; kt++) {
        const uint32_t* Sa = sm + (kt & 1) * STAGE;
        const uint32_t* Sb = Sa + BM * 36;

        if (kt < 15) {
            const int ko = (kt + 1) * 32;
#pragma unroll
            for (int i = 0; i < NA; i++) pa[i] = *(const float4*)(X + aoff[i] + ko);
#pragma unroll
            for (int i = 0; i < NB; i++) pb[i] = *(const float4*)(W + boff[i] + ko);
        }

#pragma unroll
        for (int kq = 0; kq < 2; kq++) {
            uint4 va[2][2];
#pragma unroll
            for (int mt = 0; mt < 2; mt++) {
                const int r0 = wm + mt * 16 + g;
                va[mt][0] = *(const uint4*)&Sa[r0 * 36 + slot8 + kq * 4];
                va[mt][1] = *(const uint4*)&Sa[(r0 + 8) * 36 + slot8 + kq * 4];
            }
#pragma unroll
            for (int nt = 0; nt < 4; nt++) {
                const int rB = wn + nt * 8 + g;
                uint4 vb = *(const uint4*)&Sb[rB * 36 + slot8 + kq * 4];
#pragma unroll
                for (int mt = 0; mt < 2; mt++) {
                    uint32_t a0[4] = {va[mt][0].x, va[mt][1].x, va[mt][0].y, va[mt][1].y};
                    uint32_t b0[2] = {vb.x, vb.y};
                    mma_tf32(acc[mt][nt], a0, b0);
                    uint32_t a1[4] = {va[mt][0].z, va[mt][1].z, va[mt][0].w, va[mt][1].w};
                    uint32_t b1[2] = {vb.z, vb.w};
                    mma_tf32(acc[mt][nt], a1, b1);
                }
            }
        }

        if (kt < 15) {
            uint32_t* Da = sm + ((kt + 1) & 1) * STAGE;
            uint32_t* Db = Da + BM * 36;
#pragma unroll
            for (int i = 0; i < NA; i++) {
                Da[asts[i] + ((0 ^ ax3[i]) << 3)] = f2tf32(pa[i].x);
                Da[asts[i] + ((1 ^ ax3[i]) << 3)] = f2tf32(pa[i].y);
                Da[asts[i] + ((2 ^ ax3[i]) << 3)] = f2tf32(pa[i].z);
                Da[asts[i] + ((3 ^ ax3[i]) << 3)] = f2tf32(pa[i].w);
            }
#pragma unroll
            for (int i = 0; i < NB; i++) {
                Db[bsts[i] + ((0 ^ bx3[i]) << 3)] = f2tf32(pb[i].x);
                Db[bsts[i] + ((1 ^ bx3[i]) << 3)] = f2tf32(pb[i].y);
                Db[bsts[i] + ((2 ^ bx3[i]) << 3)] = f2tf32(pb[i].z);
                Db[bsts[i] + ((3 ^ bx3[i]) << 3)] = f2tf32(pb[i].w);
            }
        }
        __syncthreads();
    }

    // ---- epilogue: bias + store (padded duplicate rows write identical
    //      values -> deterministic) ----
#pragma unroll
    for (int mt = 0; mt < 2; mt++) {
        const int lr0 = wm + mt * 16 + g;
        const int lr1 = lr0 + 8;
        const int gr0 = GATHER ? ridx[lr0] : row0 + lr0;
        const int gr1 = GATHER ? ridx[lr1] : row0 + lr1;
        float* o0 = out + (size_t)gr0 * out_ld + n0;
        float* o1 = out + (size_t)gr1 * out_ld + n0;
#pragma unroll
        for (int nt = 0; nt < 4; nt++) {
            const int c = wn + nt * 8 + 2 * tg;
            float2 s0, s1;
            s0.x = acc[mt][nt][0] + bias[c];
            s0.y = acc[mt][nt][1] + bias[c + 1];
            s1.x = acc[mt][nt][2] + bias[c];
            s1.y = acc[mt][nt][3] + bias[c + 1];
            *(float2*)(o0 + c) = s0;
            *(float2*)(o1 + c) = s1;
        }
    }
}

// ===========================================================================
extern "C" void kernel_launch(void* const* d_in, const int* in_sizes, int n_in,
                              void* d_out, int out_size) {
    const float* x  = (const float*)d_in[0];
    const float* rw = (const float*)d_in[1];
    const float* rb = (const float*)d_in[2];
    const float* ew = (const float*)d_in[3];
    const float* eb = (const float*)d_in[4];
    const float* pw = (const float*)d_in[5];
    const float* pb = (const float*)d_in[6];

    float* out      = (float*)d_out;
    float* o_idx    = out;
    float* o_probs  = out + N_TOKENS;
    float* o_adapt  = o_probs + (size_t)N_TOKENS * N_TOOLS;
    float* o_params = o_adapt + (size_t)N_TOKENS * DIM;

    // dynamic smem: 2 stages * 192 rows * 36 words * 4B + bias + ridx
    const int smem_sz = 2 * 192 * 36 * 4 + 128 * 4 + 128 * 4;

    cudaFuncSetAttribute(tc_gemm<64, 128, true>,
                         cudaFuncAttributeMaxDynamicSharedMemorySize, smem_sz);
    cudaFuncSetAttribute(tc_gemm<128, 64, false>,
                         cudaFuncAttributeMaxDynamicSharedMemorySize, smem_sz);

    zero_counts_kernel<<<1, 64>>>();
    router_kernel<<<N_TOKENS / 64, 128>>>(x, rw, rb, o_idx, o_probs);
    build_tiles_kernel<<<1, 32>>>();
    tc_gemm<128, 64, false><<<dim3(PARAM_DIM / 64, N_TOKENS / 128), 256, smem_sz>>>(
        x, pw, pb, o_params, PARAM_DIM);
    tc_gemm<64, 128, true><<<dim3(DIM / 128, 192), 256, smem_sz>>>(
        x, ew, eb, o_adapt, DIM);
}